// round 1
// baseline (speedup 1.0000x reference)
#include <cuda_runtime.h>
#include <math.h>

#define B_  2
#define C_  512
#define N_  4096
#define E_  512
#define NH  8
#define HD  64

// Scratch for projected Q/K/V in [b*NH+h][t][d] layout (head-major).
__device__ float g_Q[(size_t)B_ * NH * N_ * HD];
__device__ float g_K[(size_t)B_ * NH * N_ * HD];
__device__ float g_V[(size_t)B_ * NH * N_ * HD];

// ---------------------------------------------------------------------------
// Projection: out[b, t, e] = sum_c X[b, c, t] * W[e, c] + bias[e]
// X layout: (B, C, N) with t contiguous. Output written head-major into g_Q/K/V.
// Grid: (N/64, E/64, 3*B). 256 threads, 4x4 micro-tiles.
// ---------------------------------------------------------------------------
__global__ __launch_bounds__(256) void proj_kernel(
    const float* __restrict__ q_in, const float* __restrict__ k_in,
    const float* __restrict__ Wq, const float* __restrict__ bq,
    const float* __restrict__ Wk, const float* __restrict__ bk,
    const float* __restrict__ Wv, const float* __restrict__ bv)
{
    const int TILE = 64, KT = 32;
    __shared__ float Xs[KT][TILE];       // [c][t]
    __shared__ float Ws[TILE][KT + 1];   // [e][c], pad -> conflict-free

    int z = blockIdx.z;                  // z = proj*B + b
    int proj = z >> 1, b = z & 1;

    const float* X = (proj == 0) ? q_in : k_in;
    const float* W; const float* bias; float* outp;
    if (proj == 0)      { W = Wq; bias = bq; outp = g_Q; }
    else if (proj == 1) { W = Wk; bias = bk; outp = g_K; }
    else                { W = Wv; bias = bv; outp = g_V; }

    int t0 = blockIdx.x * TILE;
    int e0 = blockIdx.y * TILE;
    int tid = threadIdx.x;
    int tx = tid & 15, ty = tid >> 4;

    float acc[4][4];
    #pragma unroll
    for (int i = 0; i < 4; i++)
        #pragma unroll
        for (int j = 0; j < 4; j++) acc[i][j] = 0.f;

    const float* Xb = X + (size_t)b * C_ * N_;

    for (int c0 = 0; c0 < C_; c0 += KT) {
        for (int idx = tid; idx < KT * TILE; idx += 256) {
            int c = idx >> 6, t = idx & 63;
            Xs[c][t] = Xb[(size_t)(c0 + c) * N_ + t0 + t];
        }
        for (int idx = tid; idx < TILE * KT; idx += 256) {
            int e = idx >> 5, c = idx & 31;
            Ws[e][c] = W[(size_t)(e0 + e) * C_ + c0 + c];
        }
        __syncthreads();

        #pragma unroll 8
        for (int kk = 0; kk < KT; kk++) {
            float xr[4], wr[4];
            #pragma unroll
            for (int i = 0; i < 4; i++) xr[i] = Xs[kk][ty + 16 * i];
            #pragma unroll
            for (int j = 0; j < 4; j++) wr[j] = Ws[tx + 16 * j][kk];
            #pragma unroll
            for (int i = 0; i < 4; i++)
                #pragma unroll
                for (int j = 0; j < 4; j++) acc[i][j] += xr[i] * wr[j];
        }
        __syncthreads();
    }

    // e0 is 64-aligned and tile width == HD, so the whole tile is one head.
    int head = e0 >> 6;
    float* ob = outp + (size_t)(b * NH + head) * N_ * HD;
    #pragma unroll
    for (int j = 0; j < 4; j++) {
        int d = tx + 16 * j;                 // d within head
        float bv_ = bias[e0 + d];
        #pragma unroll
        for (int i = 0; i < 4; i++) {
            int t = t0 + ty + 16 * i;
            ob[(size_t)t * HD + d] = acc[i][j] + bv_;
        }
    }
}

// ---------------------------------------------------------------------------
// Flash-style causal attention.
// Grid: (64 q-tiles, B*NH). Block: 256 threads, 4x4 micro-tiles.
// Q/K/V/P smem tiles 64x64 with stride 65 (conflict-free), 66.56 KB dynamic.
// ---------------------------------------------------------------------------
__global__ __launch_bounds__(256) void attn_kernel(float* __restrict__ out)
{
    extern __shared__ float sm[];
    float* Qs = sm;                 // 64*65
    float* Ks = sm + 64 * 65;
    float* Vs = sm + 2 * 64 * 65;
    float* Ps = sm + 3 * 64 * 65;

    // Heaviest q-tiles first to reduce wave-tail imbalance.
    int qtile = (int)gridDim.x - 1 - (int)blockIdx.x;
    int bh = blockIdx.y;
    int q0 = qtile * 64;
    int tid = threadIdx.x;
    int tx = tid & 15, ty = tid >> 4;

    const float* Qg = g_Q + (size_t)bh * N_ * HD;
    const float* Kg = g_K + (size_t)bh * N_ * HD;
    const float* Vg = g_V + (size_t)bh * N_ * HD;

    for (int idx = tid; idx < 64 * 64; idx += 256) {
        int r = idx >> 6, d = idx & 63;
        Qs[r * 65 + d] = Qg[(size_t)(q0 + r) * HD + d];
    }

    float m[4], l[4], acc[4][4];
    #pragma unroll
    for (int i = 0; i < 4; i++) {
        m[i] = -1e30f; l[i] = 0.f;
        #pragma unroll
        for (int j = 0; j < 4; j++) acc[i][j] = 0.f;
    }

    for (int kt = 0; kt <= qtile; kt++) {
        int k0 = kt * 64;
        __syncthreads();  // previous iteration's Ps/Vs reads done
        for (int idx = tid; idx < 64 * 64; idx += 256) {
            int r = idx >> 6, d = idx & 63;
            Ks[r * 65 + d] = Kg[(size_t)(k0 + r) * HD + d];
            Vs[r * 65 + d] = Vg[(size_t)(k0 + r) * HD + d];
        }
        __syncthreads();

        // S = Q K^T  (per-thread 4x4)
        float s[4][4];
        #pragma unroll
        for (int i = 0; i < 4; i++)
            #pragma unroll
            for (int j = 0; j < 4; j++) s[i][j] = 0.f;

        #pragma unroll 8
        for (int d = 0; d < 64; d++) {
            float qr[4], kr[4];
            #pragma unroll
            for (int i = 0; i < 4; i++) qr[i] = Qs[(ty + 16 * i) * 65 + d];
            #pragma unroll
            for (int j = 0; j < 4; j++) kr[j] = Ks[(tx + 16 * j) * 65 + d];
            #pragma unroll
            for (int i = 0; i < 4; i++)
                #pragma unroll
                for (int j = 0; j < 4; j++) s[i][j] += qr[i] * kr[j];
        }

        // scale + causal mask (matches reference: masked score = -1e9)
        bool diag = (kt == qtile);
        #pragma unroll
        for (int i = 0; i < 4; i++) {
            int q = q0 + ty + 16 * i;
            #pragma unroll
            for (int j = 0; j < 4; j++) {
                int k = k0 + tx + 16 * j;
                float v = s[i][j] * 0.125f;       // 1/sqrt(64)
                if (diag && k > q) v = -1e9f;
                s[i][j] = v;
            }
        }

        // online softmax: row reductions across the 16-lane tx group
        #pragma unroll
        for (int i = 0; i < 4; i++) {
            float mt = fmaxf(fmaxf(s[i][0], s[i][1]), fmaxf(s[i][2], s[i][3]));
            #pragma unroll
            for (int o = 1; o < 16; o <<= 1)
                mt = fmaxf(mt, __shfl_xor_sync(0xffffffffu, mt, o));
            float mn = fmaxf(m[i], mt);
            float corr = __expf(m[i] - mn);
            float rs = 0.f;
            #pragma unroll
            for (int j = 0; j < 4; j++) {
                float p = __expf(s[i][j] - mn);
                s[i][j] = p;
                rs += p;
            }
            #pragma unroll
            for (int o = 1; o < 16; o <<= 1)
                rs += __shfl_xor_sync(0xffffffffu, rs, o);
            l[i] = l[i] * corr + rs;
            m[i] = mn;
            #pragma unroll
            for (int j = 0; j < 4; j++) acc[i][j] *= corr;
        }

        // stage P for the PV GEMM
        #pragma unroll
        for (int i = 0; i < 4; i++)
            #pragma unroll
            for (int j = 0; j < 4; j++)
                Ps[(ty + 16 * i) * 65 + tx + 16 * j] = s[i][j];
        __syncthreads();

        // O += P @ V
        #pragma unroll 8
        for (int k = 0; k < 64; k++) {
            float pr[4], vr[4];
            #pragma unroll
            for (int i = 0; i < 4; i++) pr[i] = Ps[(ty + 16 * i) * 65 + k];
            #pragma unroll
            for (int j = 0; j < 4; j++) vr[j] = Vs[k * 65 + tx + 16 * j];
            #pragma unroll
            for (int i = 0; i < 4; i++)
                #pragma unroll
                for (int j = 0; j < 4; j++) acc[i][j] += pr[i] * vr[j];
        }
    }

    // normalize + stage into smem for coalesced (B,E,N) stores
    __syncthreads();
    #pragma unroll
    for (int i = 0; i < 4; i++) {
        float inv = 1.f / l[i];
        #pragma unroll
        for (int j = 0; j < 4; j++)
            Ps[(ty + 16 * i) * 65 + tx + 16 * j] = acc[i][j] * inv;
    }
    __syncthreads();

    int b = bh >> 3, h = bh & 7;
    float* ob = out + ((size_t)b * E_ + (size_t)h * HD) * N_;
    for (int idx = tid; idx < 64 * 64; idx += 256) {
        int d = idx >> 6, r = idx & 63;
        ob[(size_t)d * N_ + q0 + r] = Ps[r * 65 + d];
    }
}

// ---------------------------------------------------------------------------

extern "C" void kernel_launch(void* const* d_in, const int* in_sizes, int n_in,
                              void* d_out, int out_size)
{
    const float* q_in = (const float*)d_in[0];
    const float* k_in = (const float*)d_in[1];
    const float* Wq   = (const float*)d_in[2];
    const float* bq   = (const float*)d_in[3];
    const float* Wk   = (const float*)d_in[4];
    const float* bk   = (const float*)d_in[5];
    const float* Wv   = (const float*)d_in[6];
    const float* bv   = (const float*)d_in[7];
    float* out = (float*)d_out;

    dim3 pg(N_ / 64, E_ / 64, 3 * B_);
    proj_kernel<<<pg, 256>>>(q_in, k_in, Wq, bq, Wk, bk, Wv, bv);

    const int smem_bytes = 4 * 64 * 65 * sizeof(float);  // 66560 B
    cudaFuncSetAttribute(attn_kernel,
                         cudaFuncAttributeMaxDynamicSharedMemorySize,
                         smem_bytes);
    dim3 ag(N_ / 64, B_ * NH);
    attn_kernel<<<ag, 256, smem_bytes>>>(out);
}

// round 3
// speedup vs baseline: 1.2684x; 1.2684x over previous
#include <cuda_runtime.h>
#include <math.h>

#define B_  2
#define C_  512
#define N_  4096
#define E_  512
#define NH  8
#define HD  64

typedef unsigned long long u64;

// Scratch for projected Q/K/V in [b*NH+h][t][d] layout (head-major).
__device__ float g_Q[(size_t)B_ * NH * N_ * HD];
__device__ float g_K[(size_t)B_ * NH * N_ * HD];
__device__ float g_V[(size_t)B_ * NH * N_ * HD];

// ---- packed f32x2 helpers (Blackwell FFMA2 path) -------------------------
__device__ __forceinline__ u64 bcast2(float x) {
    u64 r; asm("mov.b64 %0, {%1, %1};" : "=l"(r) : "f"(x)); return r;
}
__device__ __forceinline__ float2 unpack2(u64 v) {
    float2 f; asm("mov.b64 {%0, %1}, %2;" : "=f"(f.x), "=f"(f.y) : "l"(v)); return f;
}
__device__ __forceinline__ void fma2(u64& d, u64 a, u64 b) {
    asm("fma.rn.f32x2 %0, %1, %2, %0;" : "+l"(d) : "l"(a), "l"(b));
}
__device__ __forceinline__ void mul2(u64& d, u64 a) {
    asm("mul.rn.f32x2 %0, %0, %1;" : "+l"(d) : "l"(a));
}

// 16B-chunk XOR swizzle for transposed [d][q] tiles (64 x 128 floats, row
// stride 128 = 512B). Conflict-free LDS.128 row reads + low-conflict
// column (transpose) writes.
__device__ __forceinline__ int QSW(int d, int q) {
    return d * 128 + (((((q) >> 2) ^ ((d >> 2) & 7)) << 2) | (q & 3));
}

// ---------------------------------------------------------------------------
// Projection: out[b, t, e] = sum_c X[b, c, t] * W[e, c] + bias[e]
// Tile: 128 t x 64 e, 256 threads, t-paired 8x4 micro-tile via FFMA2.
// Grid: (N/128, E/64, 3*B). Each e-tile of 64 == one head.
// ---------------------------------------------------------------------------
__global__ __launch_bounds__(256) void proj_kernel(
    const float* __restrict__ q_in, const float* __restrict__ k_in,
    const float* __restrict__ Wq, const float* __restrict__ bq,
    const float* __restrict__ Wk, const float* __restrict__ bk,
    const float* __restrict__ Wv, const float* __restrict__ bv)
{
    __shared__ float Xs[32 * 128];   // [c][t], t contiguous
    __shared__ float Wt[32 * 65];    // [c][e] transposed, pad 65

    int z = blockIdx.z;              // z = proj*B + b
    int proj = z >> 1, b = z & 1;

    const float* X = (proj == 0) ? q_in : k_in;
    const float* W; const float* bias; float* outp;
    if (proj == 0)      { W = Wq; bias = bq; outp = g_Q; }
    else if (proj == 1) { W = Wk; bias = bk; outp = g_K; }
    else                { W = Wv; bias = bv; outp = g_V; }

    int t0 = blockIdx.x * 128;
    int e0 = blockIdx.y * 64;
    int tid = threadIdx.x;
    int tx = tid & 15, ty = tid >> 4;

    u64 acc[4][4];
    #pragma unroll
    for (int p = 0; p < 4; p++)
        #pragma unroll
        for (int j = 0; j < 4; j++) acc[p][j] = 0ull;

    const float* Xb = X + (size_t)b * C_ * N_;

    for (int c0 = 0; c0 < C_; c0 += 32) {
        {   // load X tile: [c][t]
            int c = tid >> 5, t4 = (tid & 31) * 4;
            #pragma unroll
            for (int cc = 0; cc < 32; cc += 8)
                *(float4*)&Xs[(c + cc) * 128 + t4] =
                    *(const float4*)&Xb[(size_t)(c0 + c + cc) * N_ + t0 + t4];
        }
        {   // load W tile transposed: Wt[c][e]
            int e = tid >> 3, c4 = (tid & 7) * 4;
            #pragma unroll
            for (int ee = 0; ee < 64; ee += 32) {
                float4 w = *(const float4*)&W[(size_t)(e0 + e + ee) * C_ + c0 + c4];
                Wt[(c4 + 0) * 65 + e + ee] = w.x;
                Wt[(c4 + 1) * 65 + e + ee] = w.y;
                Wt[(c4 + 2) * 65 + e + ee] = w.z;
                Wt[(c4 + 3) * 65 + e + ee] = w.w;
            }
        }
        __syncthreads();

        #pragma unroll 4
        for (int c = 0; c < 32; c++) {
            ulonglong2 xa = *(const ulonglong2*)&Xs[c * 128 + ty * 8];
            ulonglong2 xb2 = *(const ulonglong2*)&Xs[c * 128 + ty * 8 + 4];
            u64 tp[4] = { xa.x, xa.y, xb2.x, xb2.y };   // t pairs (0,1)(2,3)(4,5)(6,7)
            #pragma unroll
            for (int j = 0; j < 4; j++) {
                u64 wb = bcast2(Wt[c * 65 + tx + 16 * j]);
                #pragma unroll
                for (int p = 0; p < 4; p++) fma2(acc[p][j], tp[p], wb);
            }
        }
        __syncthreads();
    }

    int head = blockIdx.y;                 // e-tile == head
    float* ob = outp + (size_t)(b * NH + head) * N_ * HD;
    #pragma unroll
    for (int j = 0; j < 4; j++) {
        int d = tx + 16 * j;
        float bj = bias[e0 + d];
        #pragma unroll
        for (int p = 0; p < 4; p++) {
            float2 f = unpack2(acc[p][j]);
            int t = t0 + ty * 8 + 2 * p;
            ob[(size_t)t * HD + d]       = f.x + bj;
            ob[(size_t)(t + 1) * HD + d] = f.y + bj;
        }
    }
}

// ---------------------------------------------------------------------------
// Flash-style causal attention, 128x128 tiles, FFMA2.
// Grid: (32 q-tiles, B*NH). 256 threads.
// S GEMM: q-paired 8x8 micro-tile.  PV GEMM: d-paired 8x4 micro-tile.
// Smem: Qt/Kt transposed+swizzled (64x128), Vs natural (128x64),
//       Ps natural (128x132), reused as swizzled [d][q] output staging.
// ---------------------------------------------------------------------------
__global__ __launch_bounds__(256) void attn_kernel(float* __restrict__ out)
{
    extern __shared__ float sm[];
    float* Qt = sm;                  // 64*128 swizzled [d][q]
    float* Kt = Qt + 64 * 128;       // 64*128 swizzled [d][k]
    float* Vs = Kt + 64 * 128;       // 128*64 natural [k][d]
    float* Ps = Vs + 128 * 64;       // 128*132 natural [q][k]

    int qtile = (int)gridDim.x - 1 - (int)blockIdx.x;   // heaviest first
    int bh = blockIdx.y;
    int q0 = qtile * 128;
    int tid = threadIdx.x;
    int tx = tid & 15, ty = tid >> 4;
    int r0 = tid >> 4, d4 = tx * 4;

    const float* Qg = g_Q + (size_t)bh * N_ * HD;
    const float* Kg = g_K + (size_t)bh * N_ * HD;
    const float* Vg = g_V + (size_t)bh * N_ * HD;

    // load + transpose Q (swizzled)
    for (int r = r0; r < 128; r += 16) {
        float4 v = *(const float4*)&Qg[(size_t)(q0 + r) * HD + d4];
        Qt[QSW(d4 + 0, r)] = v.x; Qt[QSW(d4 + 1, r)] = v.y;
        Qt[QSW(d4 + 2, r)] = v.z; Qt[QSW(d4 + 3, r)] = v.w;
    }

    float m[8], l[8];
    u64 op2[8][2];                   // O acc: 8 q-rows x 2 d-pairs (d = tx*4..+3)
    #pragma unroll
    for (int r = 0; r < 8; r++) {
        m[r] = -1e30f; l[r] = 0.f;
        op2[r][0] = 0ull; op2[r][1] = 0ull;
    }

    for (int kt = 0; kt <= qtile; kt++) {
        int k0 = kt * 128;
        __syncthreads();             // prior PV reads of Ps/Vs done
        for (int r = r0; r < 128; r += 16) {
            float4 kv = *(const float4*)&Kg[(size_t)(k0 + r) * HD + d4];
            Kt[QSW(d4 + 0, r)] = kv.x; Kt[QSW(d4 + 1, r)] = kv.y;
            Kt[QSW(d4 + 2, r)] = kv.z; Kt[QSW(d4 + 3, r)] = kv.w;
            float4 vv = *(const float4*)&Vg[(size_t)(k0 + r) * HD + d4];
            *(float4*)&Vs[r * 64 + d4] = vv;
        }
        __syncthreads();

        // S = Q K^T : q-paired, rows ty*8+2p(+1), cols tx*8+c
        u64 s2[4][8];
        #pragma unroll
        for (int p = 0; p < 4; p++)
            #pragma unroll
            for (int c = 0; c < 8; c++) s2[p][c] = 0ull;

        #pragma unroll 2
        for (int d = 0; d < 64; d++) {
            int xd = (d >> 2) & 7;
            ulonglong2 qa = *(const ulonglong2*)&Qt[d * 128 + (((2 * ty) ^ xd) << 2)];
            ulonglong2 qb = *(const ulonglong2*)&Qt[d * 128 + (((2 * ty + 1) ^ xd) << 2)];
            float4 ka = *(const float4*)&Kt[d * 128 + (((2 * tx) ^ xd) << 2)];
            float4 kb = *(const float4*)&Kt[d * 128 + (((2 * tx + 1) ^ xd) << 2)];
            u64 qp[4] = { qa.x, qa.y, qb.x, qb.y };
            float kv[8] = { ka.x, ka.y, ka.z, ka.w, kb.x, kb.y, kb.z, kb.w };
            #pragma unroll
            for (int c = 0; c < 8; c++) {
                u64 kk = bcast2(kv[c]);
                #pragma unroll
                for (int p = 0; p < 4; p++) fma2(s2[p][c], qp[p], kk);
            }
        }

        // scale + mask + online softmax (per q-pair), store P to smem
        bool diag = (kt == qtile);
        #pragma unroll
        for (int p = 0; p < 4; p++) {
            float lo[8], hi[8];
            #pragma unroll
            for (int c = 0; c < 8; c++) {
                float2 f = unpack2(s2[p][c]);
                lo[c] = f.x * 0.125f;            // 1/sqrt(64)
                hi[c] = f.y * 0.125f;
            }
            int rl = 2 * p, rh = 2 * p + 1;
            if (diag) {
                int ql = q0 + 8 * ty + rl;
                #pragma unroll
                for (int c = 0; c < 8; c++) {
                    int k = k0 + 8 * tx + c;
                    if (k > ql)     lo[c] = -1e9f;
                    if (k > ql + 1) hi[c] = -1e9f;
                }
            }
            float mtl = lo[0], mth = hi[0];
            #pragma unroll
            for (int c = 1; c < 8; c++) { mtl = fmaxf(mtl, lo[c]); mth = fmaxf(mth, hi[c]); }
            #pragma unroll
            for (int o = 1; o < 16; o <<= 1) {
                mtl = fmaxf(mtl, __shfl_xor_sync(0xffffffffu, mtl, o));
                mth = fmaxf(mth, __shfl_xor_sync(0xffffffffu, mth, o));
            }
            float mnl = fmaxf(m[rl], mtl);
            float mnh = fmaxf(m[rh], mth);
            float sl = 0.f, sh = 0.f;
            #pragma unroll
            for (int c = 0; c < 8; c++) {
                lo[c] = __expf(lo[c] - mnl); sl += lo[c];
                hi[c] = __expf(hi[c] - mnh); sh += hi[c];
            }
            #pragma unroll
            for (int o = 1; o < 16; o <<= 1) {
                sl += __shfl_xor_sync(0xffffffffu, sl, o);
                sh += __shfl_xor_sync(0xffffffffu, sh, o);
            }
            float cl = __expf(m[rl] - mnl);
            float ch = __expf(m[rh] - mnh);
            l[rl] = l[rl] * cl + sl;  m[rl] = mnl;
            l[rh] = l[rh] * ch + sh;  m[rh] = mnh;
            u64 c2l = bcast2(cl), c2h = bcast2(ch);
            mul2(op2[rl][0], c2l); mul2(op2[rl][1], c2l);
            mul2(op2[rh][0], c2h); mul2(op2[rh][1], c2h);

            *(float4*)&Ps[(8 * ty + rl) * 132 + 8 * tx]     = make_float4(lo[0], lo[1], lo[2], lo[3]);
            *(float4*)&Ps[(8 * ty + rl) * 132 + 8 * tx + 4] = make_float4(lo[4], lo[5], lo[6], lo[7]);
            *(float4*)&Ps[(8 * ty + rh) * 132 + 8 * tx]     = make_float4(hi[0], hi[1], hi[2], hi[3]);
            *(float4*)&Ps[(8 * ty + rh) * 132 + 8 * tx + 4] = make_float4(hi[4], hi[5], hi[6], hi[7]);
        }
        __syncthreads();

        // O += P @ V : d-paired, P broadcast, V vector (d = tx*4..+3)
        #pragma unroll 2
        for (int k = 0; k < 128; k++) {
            ulonglong2 vv = *(const ulonglong2*)&Vs[k * 64 + d4];
            #pragma unroll
            for (int r = 0; r < 8; r++) {
                u64 pb = bcast2(Ps[(8 * ty + r) * 132 + k]);
                fma2(op2[r][0], pb, vv.x);
                fma2(op2[r][1], pb, vv.y);
            }
        }
    }

    // normalize + stage transposed [d][q] (swizzled, reuse Ps region)
    __syncthreads();
    #pragma unroll
    for (int r = 0; r < 8; r++) {
        float inv = 1.f / l[r];
        int q = 8 * ty + r;
        float2 o0 = unpack2(op2[r][0]);
        float2 o1 = unpack2(op2[r][1]);
        Ps[QSW(d4 + 0, q)] = o0.x * inv;
        Ps[QSW(d4 + 1, q)] = o0.y * inv;
        Ps[QSW(d4 + 2, q)] = o1.x * inv;
        Ps[QSW(d4 + 3, q)] = o1.y * inv;
    }
    __syncthreads();

    int b = bh >> 3, h = bh & 7;
    float* ob = out + ((size_t)b * E_ + (size_t)h * HD) * N_;
    for (int idx = tid; idx < 64 * 128; idx += 256) {
        int d = idx >> 7, q = idx & 127;
        ob[(size_t)d * N_ + q0 + q] = Ps[QSW(d, q)];
    }
}

// ---------------------------------------------------------------------------

extern "C" void kernel_launch(void* const* d_in, const int* in_sizes, int n_in,
                              void* d_out, int out_size)
{
    const float* q_in = (const float*)d_in[0];
    const float* k_in = (const float*)d_in[1];
    const float* Wq   = (const float*)d_in[2];
    const float* bq   = (const float*)d_in[3];
    const float* Wk   = (const float*)d_in[4];
    const float* bk   = (const float*)d_in[5];
    const float* Wv   = (const float*)d_in[6];
    const float* bv   = (const float*)d_in[7];
    float* out = (float*)d_out;

    dim3 pg(N_ / 128, E_ / 64, 3 * B_);
    proj_kernel<<<pg, 256>>>(q_in, k_in, Wq, bq, Wk, bk, Wv, bv);

    const int smem_bytes = (64 * 128 * 2 + 128 * 64 + 128 * 132) * 4;  // 165888
    cudaFuncSetAttribute(attn_kernel,
                         cudaFuncAttributeMaxDynamicSharedMemorySize,
                         smem_bytes);
    dim3 ag(N_ / 128, B_ * NH);
    attn_kernel<<<ag, 256, smem_bytes>>>(out);
}